// round 6
// baseline (speedup 1.0000x reference)
#include <cuda_runtime.h>
#include <cuda_fp16.h>

#define NVOX 500000
#define CH 8
#define KT 27
#define TPB 128
#define RPT 2                      // rows per thread
#define RPB (TPB * RPT)            // 256 rows per block
#define KCH 9                      // taps per smem chunk

// Static scratch (allocation-free): fp16 activations.
__device__ __align__(16) __half g_featH[NVOX * CH];  // fp16 copy of current grid input
__device__ __align__(16) __half g_bufA[NVOX * CH];
__device__ __align__(16) __half g_bufB[NVOX * CH];

__device__ __forceinline__ void ffma2(unsigned long long& d,
                                      unsigned long long a,
                                      unsigned long long b) {
    asm volatile("fma.rn.f32x2 %0, %1, %2, %0;" : "+l"(d) : "l"(a), "l"(b));
}

// half2 (packed in u32) -> (float lo, float hi) packed as f32x2 in u64.
__device__ __forceinline__ unsigned long long cvt2(unsigned int h2) {
    unsigned long long r;
    asm("{\n\t"
        ".reg .b16 h0, h1;\n\t"
        ".reg .f32 f0, f1;\n\t"
        "mov.b32 {h0, h1}, %1;\n\t"
        "cvt.f32.f16 f0, h0;\n\t"
        "cvt.f32.f16 f1, h1;\n\t"
        "mov.b64 %0, {f0, f1};\n\t"
        "}" : "=l"(r) : "r"(h2));
    return r;
}

// fp32 [N,8] -> fp16 [N,8], one row (8ch) per thread.
__global__ void __launch_bounds__(256)
cvt_f32_to_f16(const float4* __restrict__ in, uint4* __restrict__ out) {
    const int i = blockIdx.x * 256 + threadIdx.x;
    if (i >= NVOX) return;
    const float4 a = in[i * 2];
    const float4 b = in[i * 2 + 1];
    uint4 o;
    __half2 h;
    h = __floats2half2_rn(a.x, a.y); o.x = *(unsigned int*)&h;
    h = __floats2half2_rn(a.z, a.w); o.y = *(unsigned int*)&h;
    h = __floats2half2_rn(b.x, b.y); o.z = *(unsigned int*)&h;
    h = __floats2half2_rn(b.z, b.w); o.w = *(unsigned int*)&h;
    out[i] = o;
}

// One sparse-conv layer. Input fp16 rows (uint4), fp32 accumulation.
// OUTF16: write fp16 rows; else fp32 float4 pairs (+ fp32 residual if RES).
template <bool RELU, bool RES, bool OUTF16>
__global__ void __launch_bounds__(TPB, 6)
spconv_kernel(const uint4*  __restrict__ x,      // [NVOX] fp16 rows (8 halves)
              const int*    __restrict__ nbr,    // [NVOX][27]
              const float*  __restrict__ w,      // [27][8][8] (k, cin, cout)
              const float4* __restrict__ resid,  // [NVOX][2] fp32 or null
              void*         __restrict__ out_)
{
    // Weights as cin-pair f32x2: sw[k*32 + p*8 + cout] = (w[k][2p][cout], w[k][2p+1][cout])
    __shared__ __align__(16) unsigned long long sw[KT * 32];   // 6912 B
    __shared__ __align__(16) int snbr[RPB * KCH];              // 9216 B

    const int t = threadIdx.x;
    {
        for (int i = t; i < KT * 32; i += TPB) {
            const int k = i >> 5;
            const int rem = i & 31;
            const int p = rem >> 3;
            const int cout = rem & 7;
            const float lo = w[k * 64 + (2 * p) * 8 + cout];
            const float hi = w[k * 64 + (2 * p + 1) * 8 + cout];
            unsigned long long v;
            asm("mov.b64 %0, {%1, %2};" : "=l"(v) : "f"(lo), "f"(hi));
            sw[i] = v;
        }
    }

    const int base = blockIdx.x * RPB;
    const int rows = min(RPB, NVOX - base);

    int r[RPT]; bool ok[RPT];
#pragma unroll
    for (int s = 0; s < RPT; s++) {
        r[s] = base + t + TPB * s;
        ok[s] = (r[s] < NVOX);
    }

    // acc[s][cout] lanes = (partial over even cin, partial over odd cin)
    unsigned long long acc[RPT][8];
#pragma unroll
    for (int s = 0; s < RPT; s++)
#pragma unroll
        for (int q = 0; q < 8; q++) acc[s][q] = 0ull;

    uint4 R0[RPT], R1[RPT];
    int j[RPT];

#define LOAD_IDX(u, J)                                           \
    {                                                            \
        _Pragma("unroll")                                        \
        for (int s = 0; s < RPT; s++)                            \
            J[s] = ok[s] ? snbr[(t + TPB * s) * KCH + (u)] : -1; \
    }

#define LOAD_DATA(J, R)                                          \
    {                                                            \
        _Pragma("unroll")                                        \
        for (int s = 0; s < RPT; s++) {                          \
            R[s] = make_uint4(0u, 0u, 0u, 0u);                   \
            if (J[s] >= 0) R[s] = __ldg(x + J[s]);               \
        }                                                        \
    }

#define FMA_TAP(k, R)                                                        \
    {                                                                        \
        const unsigned long long* wk = sw + (k) * 32;                        \
        unsigned long long f2[RPT][4];                                       \
        _Pragma("unroll")                                                    \
        for (int s = 0; s < RPT; s++) {                                      \
            f2[s][0] = cvt2(R[s].x);                                         \
            f2[s][1] = cvt2(R[s].y);                                         \
            f2[s][2] = cvt2(R[s].z);                                         \
            f2[s][3] = cvt2(R[s].w);                                         \
        }                                                                    \
        _Pragma("unroll")                                                    \
        for (int p = 0; p < 4; p++) {                                        \
            _Pragma("unroll")                                                \
            for (int cp = 0; cp < 4; cp++) {                                 \
                const ulonglong2 wv = *(const ulonglong2*)(wk + p * 8 + cp * 2); \
                _Pragma("unroll")                                            \
                for (int s = 0; s < RPT; s++) {                              \
                    ffma2(acc[s][cp * 2],     f2[s][p], wv.x);               \
                    ffma2(acc[s][cp * 2 + 1], f2[s][p], wv.y);               \
                }                                                            \
            }                                                                \
        }                                                                    \
    }

    const int* src = nbr + (long long)base * KT;

#pragma unroll 1
    for (int g = 0; g < 3; g++) {
        const int kbase = g * KCH;
        __syncthreads();   // covers weight staging on g==0, snbr reuse after
        {
            const int tot = rows * KCH;
            for (int i = t; i < tot; i += TPB) {
                const int row = i / KCH;
                const int kk = i - row * KCH;
                snbr[i] = src[row * KT + kbase + kk];
            }
        }
        __syncthreads();

        LOAD_IDX(0, j);
        LOAD_DATA(j, R0);
#pragma unroll
        for (int u = 0; u < KCH - 1; u++) {
            LOAD_IDX(u + 1, j);
            if (u & 1) {
                LOAD_DATA(j, R0);
                FMA_TAP(kbase + u, R1);
            } else {
                LOAD_DATA(j, R1);
                FMA_TAP(kbase + u, R0);
            }
        }
        FMA_TAP(kbase + KCH - 1, R0);   // tap 8 data sits in R0
    }

    // Epilogue: fold even/odd partials, residual / relu, store.
#pragma unroll
    for (int s = 0; s < RPT; s++) {
        if (!ok[s]) continue;
        float v[8];
#pragma unroll
        for (int c = 0; c < 8; c++) {
            unsigned int lo, hi;
            asm("mov.b64 {%0, %1}, %2;" : "=r"(lo), "=r"(hi) : "l"(acc[s][c]));
            v[c] = __uint_as_float(lo) + __uint_as_float(hi);
        }
        if (RES) {
            const float4 ra = resid[r[s] * 2];
            const float4 rb = resid[r[s] * 2 + 1];
            v[0] += ra.x; v[1] += ra.y; v[2] += ra.z; v[3] += ra.w;
            v[4] += rb.x; v[5] += rb.y; v[6] += rb.z; v[7] += rb.w;
        }
        if (RELU) {
#pragma unroll
            for (int c = 0; c < 8; c++) v[c] = fmaxf(v[c], 0.f);
        }
        if (OUTF16) {
            uint4 o;
            __half2 h;
            h = __floats2half2_rn(v[0], v[1]); o.x = *(unsigned int*)&h;
            h = __floats2half2_rn(v[2], v[3]); o.y = *(unsigned int*)&h;
            h = __floats2half2_rn(v[4], v[5]); o.z = *(unsigned int*)&h;
            h = __floats2half2_rn(v[6], v[7]); o.w = *(unsigned int*)&h;
            ((uint4*)out_)[r[s]] = o;
        } else {
            float4* o = (float4*)out_;
            o[r[s] * 2]     = make_float4(v[0], v[1], v[2], v[3]);
            o[r[s] * 2 + 1] = make_float4(v[4], v[5], v[6], v[7]);
        }
    }
#undef LOAD_IDX
#undef LOAD_DATA
#undef FMA_TAP
}

extern "C" void kernel_launch(void* const* d_in, const int* in_sizes, int n_in,
                              void* d_out, int out_size) {
    (void)in_sizes; (void)n_in; (void)out_size;
    const float* feats0 = (const float*)d_in[0];
    const float* feats1 = (const float*)d_in[1];
    const float* W0     = (const float*)d_in[2];  // [3][27][8][8]
    const float* W1     = (const float*)d_in[3];
    const int*   nbr0   = (const int*)d_in[4];    // [N][27]
    const int*   nbr1   = (const int*)d_in[5];
    float* out = (float*)d_out;

    __half *featH, *bufA, *bufB;
    cudaGetSymbolAddress((void**)&featH, g_featH);
    cudaGetSymbolAddress((void**)&bufA, g_bufA);
    cudaGetSymbolAddress((void**)&bufB, g_bufB);

    const int cgrid = (NVOX + 255) / 256;
    const int grid = (NVOX + RPB - 1) / RPB;
    const int LW = KT * CH * CH;  // 1728 floats per layer

    // Grid 0
    cvt_f32_to_f16<<<cgrid, 256>>>((const float4*)feats0, (uint4*)featH);
    spconv_kernel<true,  false, true ><<<grid, TPB>>>((const uint4*)featH, nbr0, W0,          nullptr,               (void*)bufA);
    spconv_kernel<true,  false, true ><<<grid, TPB>>>((const uint4*)bufA,  nbr0, W0 + LW,     nullptr,               (void*)bufB);
    spconv_kernel<false, true,  false><<<grid, TPB>>>((const uint4*)bufB,  nbr0, W0 + 2 * LW, (const float4*)feats0, (void*)out);
    // Grid 1
    cvt_f32_to_f16<<<cgrid, 256>>>((const float4*)feats1, (uint4*)featH);
    spconv_kernel<true,  false, true ><<<grid, TPB>>>((const uint4*)featH, nbr1, W1,          nullptr,               (void*)bufA);
    spconv_kernel<true,  false, true ><<<grid, TPB>>>((const uint4*)bufA,  nbr1, W1 + LW,     nullptr,               (void*)bufB);
    spconv_kernel<false, true,  false><<<grid, TPB>>>((const uint4*)bufB,  nbr1, W1 + 2 * LW, (const float4*)feats1, (void*)(out + (size_t)NVOX * CH));
}

// round 7
// speedup vs baseline: 1.6935x; 1.6935x over previous
#include <cuda_runtime.h>

#define NVOX 500000
#define CH 8
#define KT 27
#define TPB 128
#define RPT 4                      // rows per thread
#define RPB (TPB * RPT)            // 512 rows per block
#define KCH 9                      // taps per smem chunk (3 chunks of 9)
#define HGRID ((NVOX + RPB - 1) / RPB)   // blocks per grid half (977)

// Ping-pong scratch for intermediate activations, one pair per grid.
__device__ float g_bufA0[NVOX * CH];
__device__ float g_bufB0[NVOX * CH];
__device__ float g_bufA1[NVOX * CH];
__device__ float g_bufB1[NVOX * CH];

__device__ __forceinline__ void ffma2(unsigned long long& d,
                                      unsigned long long a,
                                      unsigned long long b) {
    asm volatile("fma.rn.f32x2 %0, %1, %2, %0;" : "+l"(d) : "l"(a), "l"(b));
}

__device__ __forceinline__ unsigned long long pack2(float x) {
    unsigned long long r;
    unsigned int xb = __float_as_uint(x);
    asm("mov.b64 %0, {%1, %1};" : "=l"(r) : "r"(xb));
    return r;
}

// One sparse-conv layer over BOTH grids in a single launch.
// blockIdx.x < HGRID -> grid 0, else grid 1 (independent pointer sets).
template <bool RELU, bool RES>
__global__ void __launch_bounds__(TPB, 5)
spconv_kernel(const float4* __restrict__ x0, const float4* __restrict__ x1,
              const int*    __restrict__ nbr0, const int* __restrict__ nbr1,
              const float*  __restrict__ w0, const float* __restrict__ w1,
              const float4* __restrict__ res0, const float4* __restrict__ res1,
              float4* __restrict__ out0, float4* __restrict__ out1)
{
    // Weights as f32x2 pairs: sw[k*32 + cin*4 + p] = (w[k][cin][2p], w[k][cin][2p+1])
    __shared__ __align__(16) unsigned long long sw[KT * 32];   // 6912 B
    __shared__ __align__(16) int snbr[RPB * KCH];              // 18432 B

    const int gsel = (blockIdx.x >= HGRID);
    const float4* __restrict__ x     = gsel ? x1 : x0;
    const int*    __restrict__ nbr   = gsel ? nbr1 : nbr0;
    const float*  __restrict__ w     = gsel ? w1 : w0;
    const float4* __restrict__ resid = gsel ? res1 : res0;
    float4*       __restrict__ out   = gsel ? out1 : out0;

    {
        const unsigned long long* w2 = (const unsigned long long*)w;
        for (int i = threadIdx.x; i < KT * 32; i += TPB) sw[i] = w2[i];
    }

    const int t = threadIdx.x;
    const int base = (blockIdx.x - (gsel ? HGRID : 0)) * RPB;
    const int rows = min(RPB, NVOX - base);

    int r[RPT]; bool ok[RPT];
#pragma unroll
    for (int s = 0; s < RPT; s++) {
        r[s] = base + t + TPB * s;
        ok[s] = (r[s] < NVOX);
    }

    unsigned long long acc[RPT][4];
#pragma unroll
    for (int s = 0; s < RPT; s++)
#pragma unroll
        for (int q = 0; q < 4; q++) acc[s][q] = 0ull;

    float4 A0[RPT], B0[RPT], A1[RPT], B1[RPT];
    int j[RPT];

#define LOAD_DATA(J, A, B)                                       \
    {                                                            \
        _Pragma("unroll")                                        \
        for (int s = 0; s < RPT; s++) {                          \
            A[s] = make_float4(0.f, 0.f, 0.f, 0.f);              \
            B[s] = A[s];                                         \
            if (J[s] >= 0) {                                     \
                A[s] = __ldg(x + J[s] * 2);                      \
                B[s] = __ldg(x + J[s] * 2 + 1);                  \
            }                                                    \
        }                                                        \
    }

#define LOAD_IDX(u, J)                                           \
    {                                                            \
        _Pragma("unroll")                                        \
        for (int s = 0; s < RPT; s++)                            \
            J[s] = ok[s] ? snbr[(t + TPB * s) * KCH + (u)] : -1; \
    }

#define FMA_TAP(k, A, B)                                                    \
    {                                                                       \
        const unsigned long long* wk = sw + (k) * 32;                       \
        _Pragma("unroll")                                                   \
        for (int c = 0; c < 8; c++) {                                       \
            const ulonglong2 wA = *(const ulonglong2*)(wk + c * 4);         \
            const ulonglong2 wB = *(const ulonglong2*)(wk + c * 4 + 2);     \
            _Pragma("unroll")                                               \
            for (int s = 0; s < RPT; s++) {                                 \
                float f;                                                    \
                switch (c) {                                                \
                    case 0: f = A[s].x; break;                              \
                    case 1: f = A[s].y; break;                              \
                    case 2: f = A[s].z; break;                              \
                    case 3: f = A[s].w; break;                              \
                    case 4: f = B[s].x; break;                              \
                    case 5: f = B[s].y; break;                              \
                    case 6: f = B[s].z; break;                              \
                    default: f = B[s].w; break;                             \
                }                                                           \
                const unsigned long long p = pack2(f);                      \
                ffma2(acc[s][0], p, wA.x);                                  \
                ffma2(acc[s][1], p, wA.y);                                  \
                ffma2(acc[s][2], p, wB.x);                                  \
                ffma2(acc[s][3], p, wB.y);                                  \
            }                                                               \
        }                                                                   \
    }

    const int* src = nbr + (long long)base * KT;

#pragma unroll 1
    for (int g = 0; g < 3; g++) {
        const int kbase = g * KCH;
        __syncthreads();   // also covers weight staging on g==0
        {
            const int tot = rows * KCH;
            for (int i = t; i < tot; i += TPB) {
                const int row = i / KCH;
                const int kk = i - row * KCH;
                snbr[i] = src[row * KT + kbase + kk];
            }
        }
        __syncthreads();

        // 2-deep gather pipeline over the 9 taps of this chunk.
        LOAD_IDX(0, j);
        LOAD_DATA(j, A0, B0);
#pragma unroll
        for (int u = 0; u < KCH - 1; u++) {
            LOAD_IDX(u + 1, j);
            if (u & 1) {
                LOAD_DATA(j, A0, B0);
                FMA_TAP(kbase + u, A1, B1);
            } else {
                LOAD_DATA(j, A1, B1);
                FMA_TAP(kbase + u, A0, B0);
            }
        }
        FMA_TAP(kbase + KCH - 1, A0, B0);   // tap 8 data sits in A0/B0
    }

    // Epilogue
#pragma unroll
    for (int s = 0; s < RPT; s++) {
        if (!ok[s]) continue;
        float v[8];
#pragma unroll
        for (int i = 0; i < 4; i++) {
            unsigned int lo, hi;
            asm("mov.b64 {%0, %1}, %2;" : "=r"(lo), "=r"(hi) : "l"(acc[s][i]));
            v[2 * i]     = __uint_as_float(lo);
            v[2 * i + 1] = __uint_as_float(hi);
        }
        if (RES) {
            const float4 ra = resid[r[s] * 2];
            const float4 rb = resid[r[s] * 2 + 1];
            v[0] += ra.x; v[1] += ra.y; v[2] += ra.z; v[3] += ra.w;
            v[4] += rb.x; v[5] += rb.y; v[6] += rb.z; v[7] += rb.w;
        }
        if (RELU) {
#pragma unroll
            for (int i = 0; i < 8; i++) v[i] = fmaxf(v[i], 0.f);
        }
        out[r[s] * 2]     = make_float4(v[0], v[1], v[2], v[3]);
        out[r[s] * 2 + 1] = make_float4(v[4], v[5], v[6], v[7]);
    }
#undef LOAD_DATA
#undef LOAD_IDX
#undef FMA_TAP
}

extern "C" void kernel_launch(void* const* d_in, const int* in_sizes, int n_in,
                              void* d_out, int out_size) {
    (void)in_sizes; (void)n_in; (void)out_size;
    const float* feats0 = (const float*)d_in[0];
    const float* feats1 = (const float*)d_in[1];
    const float* W0     = (const float*)d_in[2];  // [3][27][8][8]
    const float* W1     = (const float*)d_in[3];
    const int*   nbr0   = (const int*)d_in[4];    // [N][27]
    const int*   nbr1   = (const int*)d_in[5];
    float* out = (float*)d_out;

    float *bufA0, *bufB0, *bufA1, *bufB1;
    cudaGetSymbolAddress((void**)&bufA0, g_bufA0);
    cudaGetSymbolAddress((void**)&bufB0, g_bufB0);
    cudaGetSymbolAddress((void**)&bufA1, g_bufA1);
    cudaGetSymbolAddress((void**)&bufB1, g_bufB1);

    const int grid = 2 * HGRID;        // both grids in one launch
    const int LW = KT * CH * CH;       // 1728 floats per layer

    spconv_kernel<true,  false><<<grid, TPB>>>(
        (const float4*)feats0, (const float4*)feats1, nbr0, nbr1,
        W0,          W1,          nullptr, nullptr,
        (float4*)bufA0, (float4*)bufA1);
    spconv_kernel<true,  false><<<grid, TPB>>>(
        (const float4*)bufA0, (const float4*)bufA1, nbr0, nbr1,
        W0 + LW,     W1 + LW,     nullptr, nullptr,
        (float4*)bufB0, (float4*)bufB1);
    spconv_kernel<false, true ><<<grid, TPB>>>(
        (const float4*)bufB0, (const float4*)bufB1, nbr0, nbr1,
        W0 + 2 * LW, W1 + 2 * LW,
        (const float4*)feats0, (const float4*)feats1,
        (float4*)out, (float4*)(out + (size_t)NVOX * CH));
}